// round 1
// baseline (speedup 1.0000x reference)
#include <cuda_runtime.h>
#include <cstdint>

#define B_  256
#define T_  1000
#define I_  64
#define H_  128
#define G_  384   // 3*H

// Scratch for the precomputed input projection x_proj[B][T][3H] (bias folded in).
__device__ float g_xproj[(size_t)B_ * T_ * G_];

// ---------------------------------------------------------------------------
// Kernel A: x_proj[r][g] = sum_i input[r][i] * W_ih[g][i] + b_ih[g]
// rows = B*T = 256000 (divisible by 64), cols = 384 (divisible by 96).
// Tile: 64 rows x 96 cols per block, 256 threads, each thread 4x6 outputs.
// ---------------------------------------------------------------------------
__global__ __launch_bounds__(256) void xproj_kernel(
    const float* __restrict__ input,
    const float* __restrict__ W_ih,
    const float* __restrict__ b_ih)
{
    __shared__ float As[64][65];   // pad to dodge bank conflicts on column reads
    __shared__ float Bs[64][96];   // [k][n]

    const int tid  = threadIdx.x;
    const size_t row0 = (size_t)blockIdx.x * 64;
    const int col0 = blockIdx.y * 96;

    // Load A tile: 64 rows x 64 k (K == 64 exactly), float4-coalesced.
    {
        const float4* a4 = (const float4*)(input + row0 * I_);
        for (int idx = tid; idx < 1024; idx += 256) {
            int r = idx >> 4, c = idx & 15;
            float4 v = a4[r * 16 + c];
            As[r][c * 4 + 0] = v.x;
            As[r][c * 4 + 1] = v.y;
            As[r][c * 4 + 2] = v.z;
            As[r][c * 4 + 3] = v.w;
        }
    }
    // Load B tile transposed: Bs[k][n] = W_ih[(col0+n)*64 + k].
    for (int idx = tid; idx < 6144; idx += 256) {
        int k = idx & 63, n = idx >> 6;
        Bs[k][n] = W_ih[(size_t)(col0 + n) * I_ + k];
    }
    __syncthreads();

    const int tx = tid & 15;   // column group (6 cols)
    const int ty = tid >> 4;   // row group (4 rows)

    float acc[4][6];
    #pragma unroll
    for (int i = 0; i < 4; ++i)
        #pragma unroll
        for (int jn = 0; jn < 6; ++jn) acc[i][jn] = 0.f;

    #pragma unroll 8
    for (int k = 0; k < 64; ++k) {
        float a[4], b[6];
        #pragma unroll
        for (int i = 0; i < 4; ++i) a[i] = As[ty * 4 + i][k];
        #pragma unroll
        for (int jn = 0; jn < 6; ++jn) b[jn] = Bs[k][tx * 6 + jn];
        #pragma unroll
        for (int i = 0; i < 4; ++i)
            #pragma unroll
            for (int jn = 0; jn < 6; ++jn)
                acc[i][jn] += a[i] * b[jn];
    }

    #pragma unroll
    for (int i = 0; i < 4; ++i) {
        size_t r = row0 + ty * 4 + i;
        #pragma unroll
        for (int jn = 0; jn < 6; ++jn) {
            int c = col0 + tx * 6 + jn;
            g_xproj[r * G_ + c] = acc[i][jn] + b_ih[c];
        }
    }
}

// ---------------------------------------------------------------------------
// Kernel B: the GRU recurrence. 128 CTAs, 2 batch elements per CTA,
// 384 threads (thread g computes gate row g for both batches).
// W_hh kept transposed in SMEM: Wt[k][g] -> conflict-free reads.
// h for (b, j) lives in a register of thread t = b*128 + j.
// ---------------------------------------------------------------------------
__global__ __launch_bounds__(384, 1) void gru_kernel(
    const float* __restrict__ W_hh,
    const float* __restrict__ b_hh,
    float* __restrict__ out)
{
    extern __shared__ float sm[];
    float* Wt  = sm;            // [128][384] = 49152 floats
    float* hsh = sm + 49152;    // [2][128]
    float* hg  = sm + 49408;    // [2][384]

    const int t  = threadIdx.x;
    const int b0 = blockIdx.x * 2;

    // Load and transpose W_hh into SMEM (coalesced global reads).
    for (int idx = t; idx < G_ * H_; idx += 384) {
        int g = idx >> 7, k = idx & 127;
        Wt[k * G_ + g] = W_hh[idx];
    }
    const float bh = b_hh[t];
    if (t < 256) hsh[t] = 0.f;

    const int bloc = t >> 7;     // 0/1, meaningful for t < 256
    const int j    = t & 127;
    float hreg = 0.f;

    const float* xp  = g_xproj + (size_t)(b0 + bloc) * T_ * G_ + j;
    float*       stp = out     + (size_t)(b0 + bloc) * T_ * H_ + j;
    __syncthreads();

    for (int step = 0; step < T_; ++step) {
        // Prefetch this step's input projections early; the dot loop below
        // (~1.5K cycles) hides the HBM latency.
        float xr = 0.f, xz = 0.f, xn = 0.f;
        if (t < 256) { xr = xp[0]; xz = xp[128]; xn = xp[256]; }

        // hg[b][t] = b_hh[t] + sum_k Wt[k][t] * h[b][k]
        float a0 = 0.f, a1 = 0.f;
        const float* wp = Wt + t;
        #pragma unroll
        for (int kk = 0; kk < 32; ++kk) {
            float4 h0 = *(const float4*)(hsh + kk * 4);         // broadcast
            float4 h1 = *(const float4*)(hsh + 128 + kk * 4);   // broadcast
            float w0 = wp[0 * G_], w1 = wp[1 * G_], w2 = wp[2 * G_], w3 = wp[3 * G_];
            a0 += w0 * h0.x;  a1 += w0 * h1.x;
            a0 += w1 * h0.y;  a1 += w1 * h1.y;
            a0 += w2 * h0.z;  a1 += w2 * h1.z;
            a0 += w3 * h0.w;  a1 += w3 * h1.w;
            wp += 4 * G_;
        }
        hg[t]       = a0 + bh;
        hg[G_ + t]  = a1 + bh;
        __syncthreads();   // hg ready; all hsh reads of this step are done

        if (t < 256) {
            const float* hgb = hg + bloc * G_;
            float r = __fdividef(1.f, 1.f + __expf(-(xr + hgb[j])));
            float z = __fdividef(1.f, 1.f + __expf(-(xz + hgb[j + 128])));
            float n = tanhf(xn + r * hgb[j + 256]);
            hreg = (1.f - z) * n + z * hreg;
            hsh[t] = hreg;           // safe: no one reads hsh until next barrier
            stp[0] = hreg;           // states[b][step][j]
        }
        xp  += G_;
        stp += H_;
        __syncthreads();   // new h visible before next step's dot products
    }

    // Final hidden state hT appended after states.
    if (t < 256)
        out[(size_t)B_ * T_ * H_ + (size_t)(b0 + bloc) * H_ + j] = hreg;
}

// ---------------------------------------------------------------------------
// Launcher
// ---------------------------------------------------------------------------
extern "C" void kernel_launch(void* const* d_in, const int* in_sizes, int n_in,
                              void* d_out, int out_size)
{
    const float* input = (const float*)d_in[0];   // [B, T, I]
    const float* W_ih  = (const float*)d_in[1];   // [3H, I]
    const float* W_hh  = (const float*)d_in[2];   // [3H, H]
    const float* b_ih  = (const float*)d_in[3];   // [3H]
    const float* b_hh  = (const float*)d_in[4];   // [3H]
    float* out = (float*)d_out;                   // states [B,T,H] ++ hT [B,H]

    const int smem_bytes = (49152 + 256 + 768) * (int)sizeof(float);  // 200704
    cudaFuncSetAttribute(gru_kernel, cudaFuncAttributeMaxDynamicSharedMemorySize,
                         smem_bytes);

    dim3 gridA((B_ * T_) / 64, G_ / 96);   // (4000, 4)
    xproj_kernel<<<gridA, 256>>>(input, W_ih, b_ih);

    gru_kernel<<<B_ / 2, 384, smem_bytes>>>(W_hh, b_hh, out);
}

// round 2
// speedup vs baseline: 1.4078x; 1.4078x over previous
#include <cuda_runtime.h>
#include <cstdint>

#define B_  256
#define T_  1000
#define I_  64
#define H_  128
#define G_  384   // 3*H

typedef unsigned long long u64;

// Scratch for the precomputed input projection x_proj[B][T][3H] (bias folded in).
__device__ float g_xproj[(size_t)B_ * T_ * G_];

// ---- packed fp32x2 helpers (sm_100+; doubles fp32 FMA throughput) -----------
__device__ __forceinline__ u64 fma2(u64 a, u64 b, u64 c) {
    u64 d;
    asm("fma.rn.f32x2 %0, %1, %2, %3;" : "=l"(d) : "l"(a), "l"(b), "l"(c));
    return d;
}
__device__ __forceinline__ float sum2(u64 a) {
    unsigned lo, hi;
    asm("mov.b64 {%0, %1}, %2;" : "=r"(lo), "=r"(hi) : "l"(a));
    return __uint_as_float(lo) + __uint_as_float(hi);
}

// ---------------------------------------------------------------------------
// Kernel A: x_proj[r][g] = sum_i input[r][i] * W_ih[g][i] + b_ih[g]
// ---------------------------------------------------------------------------
__global__ __launch_bounds__(256) void xproj_kernel(
    const float* __restrict__ input,
    const float* __restrict__ W_ih,
    const float* __restrict__ b_ih)
{
    __shared__ float As[64][65];
    __shared__ float Bs[64][96];

    const int tid  = threadIdx.x;
    const size_t row0 = (size_t)blockIdx.x * 64;
    const int col0 = blockIdx.y * 96;

    {
        const float4* a4 = (const float4*)(input + row0 * I_);
        for (int idx = tid; idx < 1024; idx += 256) {
            int r = idx >> 4, c = idx & 15;
            float4 v = a4[r * 16 + c];
            As[r][c * 4 + 0] = v.x;
            As[r][c * 4 + 1] = v.y;
            As[r][c * 4 + 2] = v.z;
            As[r][c * 4 + 3] = v.w;
        }
    }
    for (int idx = tid; idx < 6144; idx += 256) {
        int k = idx & 63, n = idx >> 6;
        Bs[k][n] = W_ih[(size_t)(col0 + n) * I_ + k];
    }
    __syncthreads();

    const int tx = tid & 15;
    const int ty = tid >> 4;

    float acc[4][6];
    #pragma unroll
    for (int i = 0; i < 4; ++i)
        #pragma unroll
        for (int jn = 0; jn < 6; ++jn) acc[i][jn] = 0.f;

    #pragma unroll 8
    for (int k = 0; k < 64; ++k) {
        float a[4], b[6];
        #pragma unroll
        for (int i = 0; i < 4; ++i) a[i] = As[ty * 4 + i][k];
        #pragma unroll
        for (int jn = 0; jn < 6; ++jn) b[jn] = Bs[k][tx * 6 + jn];
        #pragma unroll
        for (int i = 0; i < 4; ++i)
            #pragma unroll
            for (int jn = 0; jn < 6; ++jn)
                acc[i][jn] += a[i] * b[jn];
    }

    #pragma unroll
    for (int i = 0; i < 4; ++i) {
        size_t r = row0 + ty * 4 + i;
        #pragma unroll
        for (int jn = 0; jn < 6; ++jn) {
            int c = col0 + tx * 6 + jn;
            g_xproj[r * G_ + c] = acc[i][jn] + b_ih[c];
        }
    }
}

// ---------------------------------------------------------------------------
// Kernel B: GRU recurrence. 128 CTAs x 384 threads, 2 batch elements per CTA.
// Thread t = gate row g. W for k in [0,64) lives in REGISTERS (32 f32x2 pairs
// per thread); k in [64,128) lives in SMEM as f32x2 pairs, layout [k2][g]
// (lanes g consecutive -> conflict-free LDS.64). h pairs are read as
// LDS.128 broadcasts and used directly as f32x2 operands (no pack ops).
// ---------------------------------------------------------------------------
__global__ __launch_bounds__(384, 1) void gru_kernel(
    const float* __restrict__ W_hh,
    const float* __restrict__ b_hh,
    float* __restrict__ out)
{
    extern __shared__ float sm[];
    u64*   Wp  = (u64*)sm;          // [32][384] pairs, k2 in [32,64): 98304 B
    float* hsh = sm + 24576;        // [2][128]
    float* hg  = hsh + 256;         // [2][384]

    const int t  = threadIdx.x;
    const int b0 = blockIdx.x * 2;

    const u64* W2u = (const u64*)W_hh;   // W_hh[g][k] viewed as k-pairs

    // Register half: k2 = 0..31 for gate row t.
    u64 wreg[32];
    #pragma unroll
    for (int kk = 0; kk < 32; ++kk)
        wreg[kk] = W2u[t * 64 + kk];

    // SMEM half: Wp[kk][g] = pair k2 = 32+kk of gate row g (coalesced reads).
    for (int idx = t; idx < 32 * 384; idx += 384) {
        int g  = idx >> 5;
        int kk = idx & 31;
        Wp[kk * 384 + g] = W2u[g * 64 + 32 + kk];
    }

    const float bh = b_hh[t];
    if (t < 256) hsh[t] = 0.f;

    const int bloc = t >> 7;
    const int j    = t & 127;
    float hreg = 0.f;

    const float* xp  = g_xproj + (size_t)(b0 + bloc) * T_ * G_ + j;
    float*       stp = out     + (size_t)(b0 + bloc) * T_ * H_ + j;

    const u64* hp0 = (const u64*)hsh;          // batch0 h as k-pairs
    const u64* hp1 = (const u64*)(hsh + 128);  // batch1
    const u64* wps = Wp + t;
    __syncthreads();

    for (int step = 0; step < T_; ++step) {
        // Prefetch this step's input projections (hidden behind the dot loop).
        float xr = 0.f, xz = 0.f, xn = 0.f;
        if (t < 256) { xr = xp[0]; xz = xp[128]; xn = xp[256]; }

        u64 a0 = 0, a1 = 0, c0 = 0, c1 = 0;   // 4 independent chains

        // k = [0, 64): W in registers
        #pragma unroll
        for (int kk = 0; kk < 32; kk += 2) {
            ulonglong2 h0 = *(const ulonglong2*)(hp0 + kk);   // broadcast
            ulonglong2 h1 = *(const ulonglong2*)(hp1 + kk);   // broadcast
            a0 = fma2(wreg[kk],     h0.x, a0);
            a1 = fma2(wreg[kk],     h1.x, a1);
            c0 = fma2(wreg[kk + 1], h0.y, c0);
            c1 = fma2(wreg[kk + 1], h1.y, c1);
        }
        // k = [64, 128): W in SMEM
        #pragma unroll
        for (int kk = 0; kk < 32; kk += 2) {
            ulonglong2 h0 = *(const ulonglong2*)(hp0 + 32 + kk);
            ulonglong2 h1 = *(const ulonglong2*)(hp1 + 32 + kk);
            u64 w0 = wps[kk * 384];
            u64 w1 = wps[(kk + 1) * 384];
            a0 = fma2(w0, h0.x, a0);
            a1 = fma2(w0, h1.x, a1);
            c0 = fma2(w1, h0.y, c0);
            c1 = fma2(w1, h1.y, c1);
        }

        hg[t]       = sum2(a0) + sum2(c0) + bh;
        hg[G_ + t]  = sum2(a1) + sum2(c1) + bh;
        __syncthreads();   // hg ready; all hsh reads of this step done

        if (t < 256) {
            const float* hgb = hg + bloc * G_;
            float r = __fdividef(1.f, 1.f + __expf(-(xr + hgb[j])));
            float z = __fdividef(1.f, 1.f + __expf(-(xz + hgb[j + 128])));
            float pre = xn + r * hgb[j + 256];
            float e   = __expf(-2.f * fabsf(pre));
            float n   = copysignf(__fdividef(1.f - e, 1.f + e), pre);
            hreg = (1.f - z) * n + z * hreg;
            hsh[t] = hreg;
            stp[0] = hreg;
        }
        xp  += G_;
        stp += H_;
        __syncthreads();   // new h visible before next step's dot products
    }

    if (t < 256)
        out[(size_t)B_ * T_ * H_ + (size_t)(b0 + bloc) * H_ + j] = hreg;
}

// ---------------------------------------------------------------------------
// Launcher
// ---------------------------------------------------------------------------
extern "C" void kernel_launch(void* const* d_in, const int* in_sizes, int n_in,
                              void* d_out, int out_size)
{
    const float* input = (const float*)d_in[0];   // [B, T, I]
    const float* W_ih  = (const float*)d_in[1];   // [3H, I]
    const float* W_hh  = (const float*)d_in[2];   // [3H, H]
    const float* b_ih  = (const float*)d_in[3];   // [3H]
    const float* b_hh  = (const float*)d_in[4];   // [3H]
    float* out = (float*)d_out;

    const int smem_bytes = (24576 + 256 + 768) * (int)sizeof(float);  // 102400
    cudaFuncSetAttribute(gru_kernel, cudaFuncAttributeMaxDynamicSharedMemorySize,
                         smem_bytes);

    dim3 gridA((B_ * T_) / 64, G_ / 96);
    xproj_kernel<<<gridA, 256>>>(input, W_ih, b_ih);

    gru_kernel<<<B_ / 2, 384, smem_bytes>>>(W_hh, b_hh, out);
}

// round 3
// speedup vs baseline: 1.6460x; 1.1693x over previous
#include <cuda_runtime.h>
#include <cstdint>

#define B_  256
#define T_  1000
#define I_  64
#define H_  128
#define G_  384   // 3*H

typedef unsigned long long u64;

// Scratch for the precomputed input projection x_proj[B][T][3H] (bias folded in).
__device__ float g_xproj[(size_t)B_ * T_ * G_];

// ---- packed fp32x2 helpers (sm_100+) ----------------------------------------
__device__ __forceinline__ u64 fma2(u64 a, u64 b, u64 c) {
    u64 d;
    asm("fma.rn.f32x2 %0, %1, %2, %3;" : "=l"(d) : "l"(a), "l"(b), "l"(c));
    return d;
}
__device__ __forceinline__ float sum2(u64 a) {
    unsigned lo, hi;
    asm("mov.b64 {%0, %1}, %2;" : "=r"(lo), "=r"(hi) : "l"(a));
    return __uint_as_float(lo) + __uint_as_float(hi);
}

// ---------------------------------------------------------------------------
// Kernel A: x_proj[r][g] = sum_i input[r][i] * W_ih[g][i] + b_ih[g]
// f32x2 over k-pairs. Tile 64 rows x 96 cols, 256 threads, 4x6 per thread.
// Bs stored [n][k] (pad 66 -> conflict-free LDS.64 with stride-16 col map).
// ---------------------------------------------------------------------------
__global__ __launch_bounds__(256) void xproj_kernel(
    const float* __restrict__ input,
    const float* __restrict__ W_ih,
    const float* __restrict__ b_ih)
{
    __shared__ float As[64][68];   // [r][k], 8/16B-aligned rows (272 B)
    __shared__ float Bs[96][66];   // [n][k], 264 B rows -> 2tx bank map

    const int tid  = threadIdx.x;
    const size_t row0 = (size_t)blockIdx.x * 64;
    const int col0 = blockIdx.y * 96;

    {   // A tile: float4-coalesced
        const float4* a4 = (const float4*)(input + row0 * I_);
        for (int idx = tid; idx < 1024; idx += 256) {
            int r = idx >> 4, c = idx & 15;
            float4 v = a4[r * 16 + c];
            As[r][c * 4 + 0] = v.x;
            As[r][c * 4 + 1] = v.y;
            As[r][c * 4 + 2] = v.z;
            As[r][c * 4 + 3] = v.w;
        }
    }
    // B tile: straight copy, [n][k] (W_ih is [g][k] row-major already)
    for (int idx = tid; idx < 6144; idx += 256) {
        int k = idx & 63, n = idx >> 6;
        Bs[n][k] = W_ih[(size_t)(col0 + n) * I_ + k];
    }
    __syncthreads();

    const int tx = tid & 15;   // column lane: cols = tx + 16*jn
    const int ty = tid >> 4;   // row group (4 rows)

    u64 acc[4][6];
    #pragma unroll
    for (int i = 0; i < 4; ++i)
        #pragma unroll
        for (int jn = 0; jn < 6; ++jn) acc[i][jn] = 0;

    #pragma unroll 4
    for (int kk = 0; kk < 32; ++kk) {          // k-pairs
        u64 a[4], b[6];
        #pragma unroll
        for (int i = 0; i < 4; ++i)
            a[i] = *(const u64*)&As[ty * 4 + i][kk * 2];
        #pragma unroll
        for (int jn = 0; jn < 6; ++jn)
            b[jn] = *(const u64*)&Bs[tx + jn * 16][kk * 2];
        #pragma unroll
        for (int i = 0; i < 4; ++i)
            #pragma unroll
            for (int jn = 0; jn < 6; ++jn)
                acc[i][jn] = fma2(a[i], b[jn], acc[i][jn]);
    }

    #pragma unroll
    for (int i = 0; i < 4; ++i) {
        size_t r = row0 + ty * 4 + i;
        #pragma unroll
        for (int jn = 0; jn < 6; ++jn) {
            int c = col0 + tx + jn * 16;
            g_xproj[r * G_ + c] = sum2(acc[i][jn]) + b_ih[c];
        }
    }
}

// ---------------------------------------------------------------------------
// Kernel B: GRU recurrence. 128 CTAs x 256 threads, 2 batches per CTA.
// Thread (s = t>>7, j = t&127) owns gate rows {j, j+128, j+256} for k-half s,
// both batches. All 96 W pairs live in REGISTERS (192 regs). h is stored
// interleaved hint[k2][batch] so one LDS.128 feeds 6 fma2.
// Epilogue: k-half partials exchanged via smem (3 floats each way); thread
// (s,j) finalizes batch b = s for hidden unit j — gate math fully local.
// ---------------------------------------------------------------------------
__global__ __launch_bounds__(256, 1) void gru_kernel(
    const float* __restrict__ W_hh,
    const float* __restrict__ b_hh,
    float* __restrict__ out)
{
    __shared__ __align__(16) u64 hint[128];   // [k2][b]: index k2*2 + b
    __shared__ float part[2][3][128];         // [dest_s][gate][j]

    const int t = threadIdx.x;
    const int j = t & 127;
    const int s = t >> 7;          // k-half AND batch this thread finalizes
    const int b0 = blockIdx.x * 2;

    const u64* W2u = (const u64*)W_hh;   // W_hh[g][k] as k-pairs

    // 96 W pairs -> registers (one-time, L2-resident after first CTA).
    u64 wreg[96];
    #pragma unroll
    for (int gi = 0; gi < 3; ++gi)
        #pragma unroll
        for (int kk = 0; kk < 32; ++kk)
            wreg[gi * 32 + kk] = W2u[(size_t)(gi * 128 + j) * 64 + s * 32 + kk];

    const float bh0 = b_hh[j];
    const float bh1 = b_hh[j + 128];
    const float bh2 = b_hh[j + 256];

    ((float*)hint)[t] = 0.f;       // 256 words == whole hint
    float hreg = 0.f;

    const float* xp  = g_xproj + (size_t)(b0 + s) * T_ * G_ + j;
    float*       stp = out     + (size_t)(b0 + s) * T_ * H_ + j;

    const ulonglong2* hvec = (const ulonglong2*)hint;  // [k2] -> {b0pair,b1pair}
    const int kbase = s * 32;
    const int hw = (j >> 1) * 4 + s * 2 + (j & 1);     // word slot of h[s][j]
    __syncthreads();

    for (int step = 0; step < T_; ++step) {
        // Prefetch this step's input projections (consumed in epilogue).
        const float xr = xp[0], xz = xp[128], xn = xp[256];

        u64 a00 = 0, a01 = 0, a10 = 0, a11 = 0, a20 = 0, a21 = 0;
        #pragma unroll
        for (int kk = 0; kk < 32; ++kk) {
            ulonglong2 h2 = hvec[kbase + kk];   // broadcast: {h_b0, h_b1} @ k2
            a00 = fma2(wreg[kk],      h2.x, a00);
            a01 = fma2(wreg[kk],      h2.y, a01);
            a10 = fma2(wreg[32 + kk], h2.x, a10);
            a11 = fma2(wreg[32 + kk], h2.y, a11);
            a20 = fma2(wreg[64 + kk], h2.x, a20);
            a21 = fma2(wreg[64 + kk], h2.y, a21);
        }

        // My batch (b == s) partials; ship the other batch's to my partner.
        float m0, m1, m2, p0, p1, p2;
        if (s == 0) {
            m0 = sum2(a00); m1 = sum2(a10); m2 = sum2(a20);
            p0 = sum2(a01); p1 = sum2(a11); p2 = sum2(a21);
        } else {
            m0 = sum2(a01); m1 = sum2(a11); m2 = sum2(a21);
            p0 = sum2(a00); p1 = sum2(a10); p2 = sum2(a20);
        }
        part[1 - s][0][j] = p0;
        part[1 - s][1][j] = p1;
        part[1 - s][2][j] = p2;
        __syncthreads();

        const float hr = m0 + part[s][0][j] + bh0;
        const float hz = m1 + part[s][1][j] + bh1;
        const float hn = m2 + part[s][2][j] + bh2;

        const float r = __fdividef(1.f, 1.f + __expf(-(xr + hr)));
        const float z = __fdividef(1.f, 1.f + __expf(-(xz + hz)));
        const float pre = xn + r * hn;
        const float e   = __expf(-2.f * fabsf(pre));
        const float n   = copysignf(__fdividef(1.f - e, 1.f + e), pre);
        hreg = (1.f - z) * n + z * hreg;

        ((float*)hint)[hw] = hreg;   // h[s][j] into interleaved layout
        stp[0] = hreg;               // states[b0+s][step][j]

        xp  += G_;
        stp += H_;
        __syncthreads();             // h visible before next step's dot
    }

    // Final hidden state hT appended after states.
    out[(size_t)B_ * T_ * H_ + (size_t)(b0 + s) * H_ + j] = hreg;
}

// ---------------------------------------------------------------------------
// Launcher
// ---------------------------------------------------------------------------
extern "C" void kernel_launch(void* const* d_in, const int* in_sizes, int n_in,
                              void* d_out, int out_size)
{
    const float* input = (const float*)d_in[0];   // [B, T, I]
    const float* W_ih  = (const float*)d_in[1];   // [3H, I]
    const float* W_hh  = (const float*)d_in[2];   // [3H, H]
    const float* b_ih  = (const float*)d_in[3];   // [3H]
    const float* b_hh  = (const float*)d_in[4];   // [3H]
    float* out = (float*)d_out;

    dim3 gridA((B_ * T_) / 64, G_ / 96);   // (4000, 4)
    xproj_kernel<<<gridA, 256>>>(input, W_ih, b_ih);

    gru_kernel<<<B_ / 2, 256>>>(W_hh, b_hh, out);
}

// round 4
// speedup vs baseline: 2.0940x; 1.2721x over previous
#include <cuda_runtime.h>
#include <cstdint>

#define B_  256
#define T_  1000
#define I_  64
#define H_  128
#define G_  384   // 3*H

typedef unsigned long long u64;

// Scratch for the precomputed input projection x_proj[B][T][3H] (bias folded in).
__device__ float g_xproj[(size_t)B_ * T_ * G_];

// ---- packed fp32x2 helpers (sm_100+) ----------------------------------------
__device__ __forceinline__ u64 fma2(u64 a, u64 b, u64 c) {
    u64 d;
    asm("fma.rn.f32x2 %0, %1, %2, %3;" : "=l"(d) : "l"(a), "l"(b), "l"(c));
    return d;
}
__device__ __forceinline__ float sum2(u64 a) {
    unsigned lo, hi;
    asm("mov.b64 {%0, %1}, %2;" : "=r"(lo), "=r"(hi) : "l"(a));
    return __uint_as_float(lo) + __uint_as_float(hi);
}

// ---------------------------------------------------------------------------
// Kernel A: x_proj[r][g] = sum_i input[r][i] * W_ih[g][i] + b_ih[g]
// (measured ~83% of fp32 peak — unchanged this round)
// ---------------------------------------------------------------------------
__global__ __launch_bounds__(256) void xproj_kernel(
    const float* __restrict__ input,
    const float* __restrict__ W_ih,
    const float* __restrict__ b_ih)
{
    __shared__ float As[64][68];
    __shared__ float Bs[96][66];

    const int tid  = threadIdx.x;
    const size_t row0 = (size_t)blockIdx.x * 64;
    const int col0 = blockIdx.y * 96;

    {
        const float4* a4 = (const float4*)(input + row0 * I_);
        for (int idx = tid; idx < 1024; idx += 256) {
            int r = idx >> 4, c = idx & 15;
            float4 v = a4[r * 16 + c];
            As[r][c * 4 + 0] = v.x;
            As[r][c * 4 + 1] = v.y;
            As[r][c * 4 + 2] = v.z;
            As[r][c * 4 + 3] = v.w;
        }
    }
    for (int idx = tid; idx < 6144; idx += 256) {
        int k = idx & 63, n = idx >> 6;
        Bs[n][k] = W_ih[(size_t)(col0 + n) * I_ + k];
    }
    __syncthreads();

    const int tx = tid & 15;
    const int ty = tid >> 4;

    u64 acc[4][6];
    #pragma unroll
    for (int i = 0; i < 4; ++i)
        #pragma unroll
        for (int jn = 0; jn < 6; ++jn) acc[i][jn] = 0;

    #pragma unroll 4
    for (int kk = 0; kk < 32; ++kk) {
        u64 a[4], b[6];
        #pragma unroll
        for (int i = 0; i < 4; ++i)
            a[i] = *(const u64*)&As[ty * 4 + i][kk * 2];
        #pragma unroll
        for (int jn = 0; jn < 6; ++jn)
            b[jn] = *(const u64*)&Bs[tx + jn * 16][kk * 2];
        #pragma unroll
        for (int i = 0; i < 4; ++i)
            #pragma unroll
            for (int jn = 0; jn < 6; ++jn)
                acc[i][jn] = fma2(a[i], b[jn], acc[i][jn]);
    }

    #pragma unroll
    for (int i = 0; i < 4; ++i) {
        size_t r = row0 + ty * 4 + i;
        #pragma unroll
        for (int jn = 0; jn < 6; ++jn) {
            int c = col0 + tx + jn * 16;
            g_xproj[r * G_ + c] = sum2(acc[i][jn]) + b_ih[c];
        }
    }
}

// ---------------------------------------------------------------------------
// Kernel B: GRU recurrence. 128 CTAs x 512 threads, 2 batches per CTA.
// Thread (q = t>>7, j = t&127) handles k-quarter q of gate rows {j, j+128}
// (W in registers, 32 u64) and of gate row j+256 (W in SMEM, LDS.64),
// for both batches. h interleaved [k-pair][b] -> one LDS.128 feeds 6 fma2.
// 4-way k-quarter reduction via SMEM float4s; threads t<256 (b=q) finalize.
// ---------------------------------------------------------------------------
__global__ __launch_bounds__(512, 1) void gru_kernel(
    const float* __restrict__ W_hh,
    const float* __restrict__ b_hh,
    float* __restrict__ out)
{
    extern __shared__ __align__(16) char smraw[];
    u64*   Wn   = (u64*)smraw;                   // [64 k2][128 j]  = 65536 B
    u64*   hint = (u64*)(smraw + 65536);         // [64 k2][2 b]    = 1024 B
    float* part = (float*)(smraw + 66560);       // [3 g][2 b][128 j][4 q] = 12288 B

    const int t = threadIdx.x;
    const int j = t & 127;
    const int q = t >> 7;                        // k-quarter; batch for t<256
    const int b0 = blockIdx.x * 2;

    const u64* W2u = (const u64*)W_hh;           // W_hh[g][k] as k-pairs

    // Gates r,z quarter-slices -> registers (32 u64 = 64 regs).
    u64 wreg[32];
    #pragma unroll
    for (int gi = 0; gi < 2; ++gi)
        #pragma unroll
        for (int kk = 0; kk < 16; ++kk)
            wreg[gi * 16 + kk] = W2u[(size_t)(gi * 128 + j) * 64 + q * 16 + kk];

    // Gate n -> SMEM, layout Wn[k2][j] (coalesced global reads).
    for (int idx = t; idx < 64 * 128; idx += 512) {
        int g  = idx >> 6;        // j of gate row
        int kk = idx & 63;        // k2
        Wn[kk * 128 + g] = W2u[(size_t)(2 * 128 + g) * 64 + kk];
    }

    const float bh0 = b_hh[j];
    const float bh1 = b_hh[j + 128];
    const float bh2 = b_hh[j + 256];

    if (t < 256) ((float*)hint)[t] = 0.f;
    float hreg = 0.f;

    const float* xp  = g_xproj + (size_t)(b0 + q) * T_ * G_ + j;   // t<256 only
    float*       stp = out     + (size_t)(b0 + q) * T_ * H_ + j;

    const ulonglong2* hvec = (const ulonglong2*)hint;  // [k-pair] -> {b0, b1}
    const u64* wq = Wn + (q * 16) * 128 + j;           // my gate-n quarter
    const int hw = (j >> 1) * 4 + q * 2 + (j & 1);     // float slot of h[b=q][j]
    __syncthreads();

    for (int step = 0; step < T_; ++step) {
        // Prefetch this step's input projections (consumed after the barrier).
        float xr = 0.f, xz = 0.f, xn = 0.f;
        if (t < 256) { xr = xp[0]; xz = xp[128]; xn = xp[256]; }

        u64 a00 = 0, a01 = 0, a10 = 0, a11 = 0, a20 = 0, a21 = 0;
        #pragma unroll
        for (int kk = 0; kk < 16; ++kk) {
            ulonglong2 h2 = hvec[q * 16 + kk];   // broadcast
            u64 w2 = wq[kk * 128];               // conflict-free LDS.64
            a00 = fma2(wreg[kk],      h2.x, a00);
            a01 = fma2(wreg[kk],      h2.y, a01);
            a10 = fma2(wreg[16 + kk], h2.x, a10);
            a11 = fma2(wreg[16 + kk], h2.y, a11);
            a20 = fma2(w2,            h2.x, a20);
            a21 = fma2(w2,            h2.y, a21);
        }

        // Quarter partials -> SMEM: part[g][b][j][q]
        part[((0 * 2 + 0) * 128 + j) * 4 + q] = sum2(a00);
        part[((0 * 2 + 1) * 128 + j) * 4 + q] = sum2(a01);
        part[((1 * 2 + 0) * 128 + j) * 4 + q] = sum2(a10);
        part[((1 * 2 + 1) * 128 + j) * 4 + q] = sum2(a11);
        part[((2 * 2 + 0) * 128 + j) * 4 + q] = sum2(a20);
        part[((2 * 2 + 1) * 128 + j) * 4 + q] = sum2(a21);
        __syncthreads();

        if (t < 256) {                           // b = q
            float4 p0 = *(const float4*)&part[((0 * 2 + q) * 128 + j) * 4];
            float4 p1 = *(const float4*)&part[((1 * 2 + q) * 128 + j) * 4];
            float4 p2 = *(const float4*)&part[((2 * 2 + q) * 128 + j) * 4];
            const float hr = (p0.x + p0.y) + (p0.z + p0.w) + bh0;
            const float hz = (p1.x + p1.y) + (p1.z + p1.w) + bh1;
            const float hn = (p2.x + p2.y) + (p2.z + p2.w) + bh2;

            const float r = __fdividef(1.f, 1.f + __expf(-(xr + hr)));
            const float z = __fdividef(1.f, 1.f + __expf(-(xz + hz)));
            const float pre = xn + r * hn;
            const float e   = __expf(-2.f * fabsf(pre));
            const float n   = copysignf(__fdividef(1.f - e, 1.f + e), pre);
            hreg = (1.f - z) * n + z * hreg;

            ((float*)hint)[hw] = hreg;
            stp[0] = hreg;
        }
        xp  += G_;
        stp += H_;
        __syncthreads();                         // h visible for next step
    }

    if (t < 256)
        out[(size_t)B_ * T_ * H_ + (size_t)(b0 + q) * H_ + j] = hreg;
}

// ---------------------------------------------------------------------------
// Launcher
// ---------------------------------------------------------------------------
extern "C" void kernel_launch(void* const* d_in, const int* in_sizes, int n_in,
                              void* d_out, int out_size)
{
    const float* input = (const float*)d_in[0];   // [B, T, I]
    const float* W_ih  = (const float*)d_in[1];   // [3H, I]
    const float* W_hh  = (const float*)d_in[2];   // [3H, H]
    const float* b_ih  = (const float*)d_in[3];   // [3H]
    const float* b_hh  = (const float*)d_in[4];   // [3H]
    float* out = (float*)d_out;

    const int smem_bytes = 65536 + 1024 + 12288;  // 78848
    cudaFuncSetAttribute(gru_kernel, cudaFuncAttributeMaxDynamicSharedMemorySize,
                         smem_bytes);

    dim3 gridA((B_ * T_) / 64, G_ / 96);   // (4000, 4)
    xproj_kernel<<<gridA, 256>>>(input, W_ih, b_ih);

    gru_kernel<<<B_ / 2, 512, smem_bytes>>>(W_hh, b_hh, out);
}